// round 12
// baseline (speedup 1.0000x reference)
#include <cuda_runtime.h>
#include <cstdint>

// Problem constants (Pose_Loss: B=65536, D=154)
#define BB   65536
#define DD   154
#define N4   ((BB * DD) / 4)        // 2,523,136 float4s per array

#define BLOCK_THREADS 256
#define BATCH 8                     // float4s per thread per inner pass
#define PASS  (BLOCK_THREADS * BATCH)   // 2048 float4s per pass
#define NPASS 2                     // passes per block
#define FPB   (PASS * NPASS)        // 4096 float4s per block
#define APB   (N4 / FPB)            // 616 blocks per array
static_assert(N4 == APB * FPB, "exact partition");
#define GRID_BLOCKS (4 * APB)       // 2464

// Scratch (allocation-free device globals; zero at load, re-zeroed each exec)
__device__ double        g_acc[2];   // [0]=recon, [1]=KLD
__device__ int           g_count;
__device__ unsigned int  g_done;

__global__ void __launch_bounds__(BLOCK_THREADS)
fused_pose_loss(const float4* __restrict__ rl, const float4* __restrict__ rr,
                const float4* __restrict__ kl, const float4* __restrict__ kr,
                const int* __restrict__ lr,    const int* __restrict__ fpose,
                float* __restrict__ out, int out_size) {
    const int tid = threadIdx.x;
    const unsigned gtid = blockIdx.x * BLOCK_THREADS + tid;

    // ---- Phase A: per-row count (2464*256 = 630K threads > BB) ----
    int c = 0;
    if (gtid < BB) {
        int l = lr[gtid];
        if (fpose[gtid] != -1)
            c = (l != 1 ? 1 : 0) + (l != 0 ? 1 : 0);
    }

    // ---- Phase B: single-array contiguous streaming reduction ----
    const unsigned aid = blockIdx.x / APB;          // which array (uniform/block)
    const unsigned seg = blockIdx.x - aid * APB;    // which chunk
    const float4* src = (aid == 0) ? rl : (aid == 1) ? rr
                      : (aid == 2) ? kl : kr;
    // weight: left arrays (aid 0,2) use (lr != 1); right arrays use (lr != 0)
    const int lneq = (aid & 1) ? 0 : 1;

    float acc = 0.0f;
    const unsigned base4 = seg * FPB;

    #pragma unroll
    for (int it = 0; it < NPASS; it++) {
        // batch 8 coalesced streaming loads (evict-first; no reuse)
        float4 v[BATCH];
        #pragma unroll
        for (int j = 0; j < BATCH; j++)
            v[j] = __ldcs(&src[base4 + it * PASS + j * BLOCK_THREADS + tid]);

        #pragma unroll
        for (int j = 0; j < BATCH; j++) {
            unsigned i    = base4 + it * PASS + j * BLOCK_THREADS + tid;
            unsigned eb   = i * 4u;
            unsigned row0 = eb / DD;                 // udiv -> mul-hi
            unsigned rem  = eb - row0 * DD;

            int l0 = lr[row0], f0 = fpose[row0];
            float w0 = (f0 != -1 && l0 != lneq) ? 1.0f : 0.0f;

            float4 x = v[j];
            if (rem <= (unsigned)(DD - 4)) {
                acc += w0 * ((x.x + x.y) + (x.z + x.w));
            } else {
                int l1 = lr[row0 + 1], f1 = fpose[row0 + 1];
                float w1 = (f1 != -1 && l1 != lneq) ? 1.0f : 0.0f;
                float xe[4] = {x.x, x.y, x.z, x.w};
                #pragma unroll
                for (int e = 0; e < 4; e++)
                    acc += (((rem + e) >= (unsigned)DD) ? w1 : w0) * xe[e];
            }
        }
    }

    double dacc = (double)acc;

    // ---- Phase C: block reduction (one double + count) ----
    #pragma unroll
    for (int off = 16; off > 0; off >>= 1) {
        dacc += __shfl_down_sync(0xFFFFFFFFu, dacc, off);
        c    += __shfl_down_sync(0xFFFFFFFFu, c,    off);
    }

    __shared__ double s_a[8];
    __shared__ int    s_c[8];
    int wid = tid >> 5;
    int lid = tid & 31;
    if (lid == 0) { s_a[wid] = dacc; s_c[wid] = c; }
    __syncthreads();

    if (wid == 0) {
        double ba = (lid < 8) ? s_a[lid] : 0.0;
        int    bc = (lid < 8) ? s_c[lid] : 0;
        #pragma unroll
        for (int off = 4; off > 0; off >>= 1) {
            ba += __shfl_down_sync(0xFFFFFFFFu, ba, off);
            bc += __shfl_down_sync(0xFFFFFFFFu, bc, off);
        }
        if (lid == 0) {
            atomicAdd(&g_acc[aid >> 1], ba);   // 0,1 -> recon ; 2,3 -> KLD
            if (bc) atomicAdd(&g_count, bc);
        }
    }

    // ---- Phase D: last-block finalize + reset ----
    __shared__ bool is_last;
    if (tid == 0) {
        __threadfence();
        unsigned tkt = atomicAdd(&g_done, 1u);
        is_last = (tkt == gridDim.x - 1);
    }
    __syncthreads();
    if (is_last && tid == 0) {
        __threadfence();
        double vr = g_acc[0];
        double vk = g_acc[1];
        int    vc = g_count;
        if (out_size > 0) out[0] = (float)(vr / 154.0);
        if (out_size > 1) out[1] = (float)vk;
        if (out_size > 2) out[2] = (float)vc;
        g_acc[0] = 0.0;
        g_acc[1] = 0.0;
        g_count  = 0;
        __threadfence();
        g_done   = 0;
    }
}

extern "C" void kernel_launch(void* const* d_in, const int* in_sizes, int n_in,
                              void* d_out, int out_size) {
    const float4* rl = (const float4*)d_in[0];
    const float4* rr = (const float4*)d_in[1];
    const float4* kl = (const float4*)d_in[2];
    const float4* kr = (const float4*)d_in[3];
    const int* lr    = (const int*)d_in[4];
    const int* fpose = (const int*)d_in[5];
    float* out = (float*)d_out;

    fused_pose_loss<<<GRID_BLOCKS, BLOCK_THREADS>>>(rl, rr, kl, kr, lr, fpose,
                                                    out, out_size);
}

// round 13
// speedup vs baseline: 1.3154x; 1.3154x over previous
#include <cuda_runtime.h>
#include <cstdint>

// Problem constants (Pose_Loss: B=65536, D=154)
#define BB   65536
#define DD   154
#define N4   ((BB * DD) / 4)        // 2,523,136 float4s per array

#define BLOCK_THREADS 256
#define T4   512                    // float4s per array per tile
#define TILE_BYTES (T4 * 16)        // 8192 B per array per tile
#define NTILES (N4 / T4)            // 4928
#define GRID_BLOCKS 448
#define TPB (NTILES / GRID_BLOCKS)  // 11 contiguous tiles per block
static_assert(N4 == NTILES * T4, "exact");
static_assert(NTILES == GRID_BLOCKS * TPB, "perfect balance");

// Scratch (allocation-free device globals; zero at load, re-zeroed each exec)
__device__ double        g_acc[2];   // [0]=recon, [1]=KLD
__device__ int           g_count;
__device__ unsigned int  g_done;

__device__ __forceinline__ void l2_prefetch(const void* p) {
    asm volatile("prefetch.global.L2 [%0];" :: "l"(p));
}

__device__ __forceinline__ float2 row_weights(int l, int f) {
    // lr in {0,1,2}: use_l <=> l != 1 ; use_r <=> l != 0 ; gated by f != -1
    bool valid = (f != -1);
    return make_float2((valid && l != 1) ? 1.0f : 0.0f,
                       (valid && l != 0) ? 1.0f : 0.0f);
}

__global__ void __launch_bounds__(BLOCK_THREADS)
fused_pose_loss(const float4* __restrict__ rl, const float4* __restrict__ rr,
                const float4* __restrict__ kl, const float4* __restrict__ kr,
                const int* __restrict__ lr,    const int* __restrict__ fpose,
                float* __restrict__ out, int out_size) {
    const int tid = threadIdx.x;
    const unsigned gtid = blockIdx.x * BLOCK_THREADS + tid;

    // ---- Phase A: per-row count (448*256 = 114,688 threads > BB) ----
    int c = 0;
    if (gtid < BB) {
        int l = lr[gtid];
        if (fpose[gtid] != -1)
            c = (l != 1 ? 1 : 0) + (l != 0 ? 1 : 0);
    }

    // Each block owns TPB contiguous tiles.
    const unsigned t0 = blockIdx.x * TPB;

    // prefetch mapping: thread -> (array, line). 4 arrays x 64 lines = 256.
    const char* pf_base = (tid < 64)  ? (const char*)rl
                        : (tid < 128) ? (const char*)rr
                        : (tid < 192) ? (const char*)kl
                                      : (const char*)kr;
    const unsigned pf_line = (tid & 63) * 128;

    // prime: prefetch first tile
    l2_prefetch(pf_base + (size_t)t0 * TILE_BYTES + pf_line);

    double racc = 0.0, kacc = 0.0;

    for (unsigned k = 0; k < TPB; k++) {
        const unsigned t = t0 + k;

        // prefetch NEXT tile's 256 lines (one per thread) into L2
        if (k + 1 < TPB)
            l2_prefetch(pf_base + (size_t)(t + 1) * TILE_BYTES + pf_line);

        // batch all 8 loads (2 float4 per array) — should be L2 hits
        const unsigned i0 = t * T4 + tid;
        const unsigned i1 = i0 + BLOCK_THREADS;
        float4 a0 = rl[i0], a1 = rl[i1];
        float4 b0 = rr[i0], b1 = rr[i1];
        float4 c0 = kl[i0], c1 = kl[i1];
        float4 d0 = kr[i0], d1 = kr[i1];

        float rt = 0.0f, kt = 0.0f;
        #pragma unroll
        for (int j = 0; j < 2; j++) {
            unsigned i = j ? i1 : i0;
            float4 a = j ? a1 : a0;
            float4 b = j ? b1 : b0;
            float4 cc = j ? c1 : c0;
            float4 d = j ? d1 : d0;

            unsigned eb   = i * 4u;
            unsigned row0 = eb / DD;              // udiv -> mul-hi
            unsigned rem  = eb - row0 * DD;
            float2 w0 = row_weights(lr[row0], fpose[row0]);   // L1-resident

            if (rem <= (unsigned)(DD - 4)) {
                rt += w0.x * ((a.x + a.y) + (a.z + a.w))
                    + w0.y * ((b.x + b.y) + (b.z + b.w));
                kt += w0.x * ((cc.x + cc.y) + (cc.z + cc.w))
                    + w0.y * ((d.x + d.y) + (d.z + d.w));
            } else {
                float2 w1 = row_weights(lr[row0 + 1], fpose[row0 + 1]);
                float ae[4] = {a.x, a.y, a.z, a.w};
                float be[4] = {b.x, b.y, b.z, b.w};
                float ce[4] = {cc.x, cc.y, cc.z, cc.w};
                float de[4] = {d.x, d.y, d.z, d.w};
                #pragma unroll
                for (int e = 0; e < 4; e++) {
                    float2 w = ((rem + e) >= (unsigned)DD) ? w1 : w0;
                    rt += w.x * ae[e] + w.y * be[e];
                    kt += w.x * ce[e] + w.y * de[e];
                }
            }
        }
        racc += (double)rt;
        kacc += (double)kt;
    }

    // ---- Phase C: block reduction ----
    #pragma unroll
    for (int off = 16; off > 0; off >>= 1) {
        racc += __shfl_down_sync(0xFFFFFFFFu, racc, off);
        kacc += __shfl_down_sync(0xFFFFFFFFu, kacc, off);
        c    += __shfl_down_sync(0xFFFFFFFFu, c,    off);
    }

    __shared__ double s_r[8], s_k[8];
    __shared__ int    s_c[8];
    int wid = tid >> 5;
    int lid = tid & 31;
    if (lid == 0) { s_r[wid] = racc; s_k[wid] = kacc; s_c[wid] = c; }
    __syncthreads();

    if (wid == 0) {
        double br = (lid < 8) ? s_r[lid] : 0.0;
        double bk = (lid < 8) ? s_k[lid] : 0.0;
        int    bc = (lid < 8) ? s_c[lid] : 0;
        #pragma unroll
        for (int off = 4; off > 0; off >>= 1) {
            br += __shfl_down_sync(0xFFFFFFFFu, br, off);
            bk += __shfl_down_sync(0xFFFFFFFFu, bk, off);
            bc += __shfl_down_sync(0xFFFFFFFFu, bc, off);
        }
        if (lid == 0) {
            atomicAdd(&g_acc[0], br);
            atomicAdd(&g_acc[1], bk);
            if (bc) atomicAdd(&g_count, bc);
        }
    }

    // ---- Phase D: last-block finalize + reset ----
    __shared__ bool is_last;
    if (tid == 0) {
        __threadfence();
        unsigned tkt = atomicAdd(&g_done, 1u);
        is_last = (tkt == gridDim.x - 1);
    }
    __syncthreads();
    if (is_last && tid == 0) {
        __threadfence();
        double vr = g_acc[0];
        double vk = g_acc[1];
        int    vc = g_count;
        if (out_size > 0) out[0] = (float)(vr / 154.0);
        if (out_size > 1) out[1] = (float)vk;
        if (out_size > 2) out[2] = (float)vc;
        g_acc[0] = 0.0;
        g_acc[1] = 0.0;
        g_count  = 0;
        __threadfence();
        g_done   = 0;
    }
}

extern "C" void kernel_launch(void* const* d_in, const int* in_sizes, int n_in,
                              void* d_out, int out_size) {
    const float4* rl = (const float4*)d_in[0];
    const float4* rr = (const float4*)d_in[1];
    const float4* kl = (const float4*)d_in[2];
    const float4* kr = (const float4*)d_in[3];
    const int* lr    = (const int*)d_in[4];
    const int* fpose = (const int*)d_in[5];
    float* out = (float*)d_out;

    fused_pose_loss<<<GRID_BLOCKS, BLOCK_THREADS>>>(rl, rr, kl, kr, lr, fpose,
                                                    out, out_size);
}